// round 6
// baseline (speedup 1.0000x reference)
#include <cuda_runtime.h>
#include <cstdint>

// One row per warp, 8 warps (256 threads) per block.
#define RPB 8
#define MAX_PARTIALS 32768
__device__ float g_partials[MAX_PARTIALS];
__device__ unsigned int g_count = 0;

typedef unsigned long long u64;
typedef unsigned int u32;

// ---- Blackwell packed f32x2 helpers (FFMA2 path, PTX-only) ----
__device__ __forceinline__ u64 pack2(float a) {
    u32 b = __float_as_uint(a);
    return ((u64)b << 32) | (u64)b;
}
__device__ __forceinline__ u64 fma2(u64 a, u64 b, u64 c) {
    u64 d;
    asm("fma.rn.f32x2 %0, %1, %2, %3;" : "=l"(d) : "l"(a), "l"(b), "l"(c));
    return d;
}
__device__ __forceinline__ u64 add2(u64 a, u64 b) {
    u64 d;
    asm("add.rn.f32x2 %0, %1, %2;" : "=l"(d) : "l"(a), "l"(b));
    return d;
}

// Scalar fast exp (tail + target gather). FFMA-only.
__device__ __forceinline__ float fexp(float x) {
    float z  = fmaf(x, 1.4426950408889634f, 12582912.0f);
    float nf = z - 12582912.0f;
    float f  = fmaf(x, 1.4426950408889634f, -nf);
    float p = fmaf(f,
               fmaf(f,
                fmaf(f, 0.05550410866482158f, 0.24022650695910072f),
                0.6931471805599453f),
               1.0f);
    // low 9 bits of 0x4B400000 are 0  =>  (z_bits<<23) == n<<23 (mod 2^32)
    return __uint_as_float(__float_as_uint(p) + __float_as_uint(z) * 8388608u);
}

// Packed pair exp: returns bits of (exp(x_hi):exp(x_lo)) as u64.
__device__ __forceinline__ u64 fexp2(u64 x2, u64 L2E, u64 MAG, u64 NEG1,
                                     u64 C3, u64 C2, u64 C1, u64 ONE) {
    u64 z   = fma2(x2, L2E, MAG);        // 12582912 + n (exact)
    u64 nfn = fma2(z, NEG1, MAG);        // -(z - MAG) = -n_float
    u64 f   = fma2(x2, L2E, nfn);        // frac in [-0.5, 0.5]
    u64 p   = fma2(f, C3, C2);
    p       = fma2(f, p, C1);
    p       = fma2(f, p, ONE);           // 2^f
    u32 rlo = (u32)p         + (u32)z         * 8388608u;   // IMAD: + n<<23
    u32 rhi = (u32)(p >> 32) + (u32)(z >> 32) * 8388608u;
    return ((u64)rhi << 32) | (u64)rlo;
}

__global__ void __launch_bounds__(256)
mae_kernel(const float* __restrict__ logits,
           const int* __restrict__ targets,     // int32 (JAX demotes int64)
           float* __restrict__ out,
           int B, int C, float invB, int nblocks)
{
    const int lane = threadIdx.x & 31;
    const int warp = threadIdx.x >> 5;
    const int row  = blockIdx.x * RPB + warp;

    __shared__ float s_p[RPB];
    __shared__ bool  s_last;

    const u64 L2E  = pack2(1.4426950408889634f);
    const u64 MAG  = pack2(12582912.0f);
    const u64 NEG1 = pack2(-1.0f);
    const u64 C3   = pack2(0.05550410866482158f);
    const u64 C2   = pack2(0.24022650695910072f);
    const u64 C1   = pack2(0.6931471805599453f);
    const u64 ONE  = pack2(1.0f);
    const u64 FILL = pack2(-80.0f);      // exp(-80) ~ 2^-115: negligible

    float p_t = 0.0f;
    if (row < B) {
        const size_t base = (size_t)row * (size_t)C;
        const ulonglong2* rp =
            reinterpret_cast<const ulonglong2*>(logits + base);
        const int C4 = C >> 2;

        // Front-batch 8 independent 16B loads per thread (MLP=8),
        // covering 8*32*4 = 1024 >= C elements. OOB slots -> -80.
        u64 v[16];
        #pragma unroll
        for (int k = 0; k < 8; k++) {
            int j = lane + (k << 5);
            if (j < C4) {
                ulonglong2 t = rp[j];
                v[2 * k]     = t.x;          // (y:x)
                v[2 * k + 1] = t.y;          // (w:z)
            } else {
                v[2 * k]     = FILL;
                v[2 * k + 1] = FILL;
            }
        }

        // Target gather overlaps with poly evaluation below.
        float ext = 0.0f;
        if (lane == 0) {
            int t = targets[row];
            t = (t < 0) ? 0 : ((t >= C) ? C - 1 : t);
            ext = fexp(__ldg(logits + base + (size_t)t));
        }

        u64 accA = 0ULL, accB = 0ULL;    // packed (0.0, 0.0)
        #pragma unroll
        for (int k = 0; k < 8; k++) {
            accA = add2(accA, fexp2(v[2 * k],     L2E, MAG, NEG1, C3, C2, C1, ONE));
            accB = add2(accB, fexp2(v[2 * k + 1], L2E, MAG, NEG1, C3, C2, C1, ONE));
        }

        // Generic tails (unused for C=1000, kept for safety).
        float tacc = 0.0f;
        for (int c = (C4 << 2) + lane; c < C; c += 32)
            tacc += fexp(logits[base + c]);
        for (int j = lane + 256; j < C4; j += 32) {
            const float* q = logits + base + 4 * (size_t)j;
            tacc += fexp(q[0]) + fexp(q[1]) + fexp(q[2]) + fexp(q[3]);
        }

        float acc = (__uint_as_float((u32)accA) + __uint_as_float((u32)(accA >> 32)))
                  + (__uint_as_float((u32)accB) + __uint_as_float((u32)(accB >> 32)))
                  + tacc;

        #pragma unroll
        for (int o = 16; o; o >>= 1)
            acc += __shfl_xor_sync(0xFFFFFFFFu, acc, o);

        if (lane == 0) p_t = ext / acc;
    }

    // ---- block reduction ----
    if (lane == 0) s_p[warp] = p_t;
    __syncthreads();

    if (threadIdx.x == 0) {
        float bsum = 0.0f;
        #pragma unroll
        for (int w = 0; w < RPB; w++) bsum += s_p[w];
        g_partials[blockIdx.x] = bsum;
        __threadfence();
        unsigned int t = atomicAdd(&g_count, 1u);
        s_last = (t == (unsigned)nblocks - 1u);
    }
    __syncthreads();

    // ---- last arriving block: deterministic-order final reduction ----
    if (s_last) {
        __shared__ float sh[8];
        float s = 0.0f;
        for (int i = threadIdx.x; i < nblocks; i += 256)
            s += __ldcg(&g_partials[i]);

        #pragma unroll
        for (int o = 16; o; o >>= 1)
            s += __shfl_xor_sync(0xFFFFFFFFu, s, o);
        if (lane == 0) sh[warp] = s;
        __syncthreads();

        if (threadIdx.x < 32) {
            float v2 = (threadIdx.x < 8) ? sh[threadIdx.x] : 0.0f;
            #pragma unroll
            for (int o = 16; o; o >>= 1)
                v2 += __shfl_xor_sync(0xFFFFFFFFu, v2, o);
            if (threadIdx.x == 0) {
                out[0] = 2.0f - 2.0f * v2 * invB;
                g_count = 0;   // reset for next graph replay
            }
        }
    }
}

extern "C" void kernel_launch(void* const* d_in, const int* in_sizes, int n_in,
                              void* d_out, int out_size)
{
    const float* logits  = (const float*)d_in[0];
    const int*   targets = (const int*)d_in[1];
    float*       out     = (float*)d_out;

    const int B = in_sizes[1];
    const int C = in_sizes[0] / B;

    int grid = (B + RPB - 1) / RPB;        // 16384 for B=131072
    if (grid > MAX_PARTIALS) grid = MAX_PARTIALS;

    mae_kernel<<<grid, 256>>>(logits, targets, out, B, C, 1.0f / (float)B, grid);
}

// round 9
// speedup vs baseline: 1.1252x; 1.1252x over previous
#include <cuda_runtime.h>
#include <cstdint>

// One row per warp, 8 warps (256 threads) per block.
#define RPB 8
#define MAX_PARTIALS 32768
__device__ float g_partials[MAX_PARTIALS];
__device__ unsigned int g_count = 0;

// Fast exp(x): round-trick + degree-2 poly of 2^f, exponent folded in with a
// single IMAD (low 9 bits of 0x4B400000 are zero => z_bits*2^23 == n<<23 mod 2^32).
// 5 float ops + 1 IMAD. Max per-element rel err ~0.7%; numerator and
// denominator of p_t share the bias, residual answer error ~1e-5.
__device__ __forceinline__ float fexp(float x) {
    float z = fmaf(x, 1.4426950408889634f, 12582912.0f);   // 12582912 + n
    float d = 12582912.0f - z;                             // -n
    float f = fmaf(x, 1.4426950408889634f, d);             // frac in [-0.5,0.5]
    float p = fmaf(f, 0.24022650695910072f, 0.6931471805599453f);
    p       = fmaf(f, p, 1.0f);                            // ~2^f
    return __uint_as_float(__float_as_uint(p) +
                           __float_as_uint(z) * 8388608u); // * 2^n
}

__global__ void __launch_bounds__(256)
mae_kernel(const float* __restrict__ logits,
           const int* __restrict__ targets,     // int32 (JAX demotes int64)
           float* __restrict__ out,
           int B, int C, float invB, int nblocks)
{
    const int lane = threadIdx.x & 31;
    const int warp = threadIdx.x >> 5;
    const int row  = blockIdx.x * RPB + warp;

    __shared__ float s_p[RPB];
    __shared__ bool  s_last;

    float p_t = 0.0f;
    if (row < B) {
        const size_t base = (size_t)row * (size_t)C;
        const float4* rp = reinterpret_cast<const float4*>(logits + base);
        const int C4 = C >> 2;

        // Front-batch 8 independent 16B loads per thread (MLP=8), covering
        // 8*32*4 = 1024 >= C elements. OOB slots -> -80 (exp ~ 2^-115 ~ 0).
        float4 v[8];
        #pragma unroll
        for (int k = 0; k < 8; k++) {
            int j = lane + (k << 5);
            if (j < C4) v[k] = rp[j];
            else        v[k] = make_float4(-80.0f, -80.0f, -80.0f, -80.0f);
        }

        // Target gather overlaps the poly evaluation below.
        float ext = 0.0f;
        if (lane == 0) {
            int t = targets[row];
            t = (t < 0) ? 0 : ((t >= C) ? C - 1 : t);
            ext = fexp(__ldg(logits + base + (size_t)t));
        }

        float a0 = 0.0f, a1 = 0.0f, a2 = 0.0f, a3 = 0.0f;
        #pragma unroll
        for (int k = 0; k < 8; k++) {
            a0 += fexp(v[k].x);
            a1 += fexp(v[k].y);
            a2 += fexp(v[k].z);
            a3 += fexp(v[k].w);
        }
        // Generic tails (unused for C=1000, kept for safety).
        for (int c = (C4 << 2) + lane; c < C; c += 32)
            a0 += fexp(logits[base + c]);
        for (int j = lane + 256; j < C4; j += 32) {
            float4 w = rp[j];
            a0 += fexp(w.x); a1 += fexp(w.y); a2 += fexp(w.z); a3 += fexp(w.w);
        }

        float acc = (a0 + a1) + (a2 + a3);
        #pragma unroll
        for (int o = 16; o; o >>= 1)
            acc += __shfl_xor_sync(0xFFFFFFFFu, acc, o);

        if (lane == 0) p_t = ext / acc;
    }

    // ---- block reduction ----
    if (lane == 0) s_p[warp] = p_t;
    __syncthreads();

    if (threadIdx.x == 0) {
        float bsum = 0.0f;
        #pragma unroll
        for (int w = 0; w < RPB; w++) bsum += s_p[w];
        g_partials[blockIdx.x] = bsum;
        __threadfence();
        unsigned int t = atomicAdd(&g_count, 1u);
        s_last = (t == (unsigned)nblocks - 1u);
    }
    __syncthreads();

    // ---- last arriving block: deterministic-order final reduction ----
    if (s_last) {
        __shared__ float sh[8];
        float s = 0.0f;
        for (int i = threadIdx.x; i < nblocks; i += 256)
            s += __ldcg(&g_partials[i]);

        #pragma unroll
        for (int o = 16; o; o >>= 1)
            s += __shfl_xor_sync(0xFFFFFFFFu, s, o);
        if (lane == 0) sh[warp] = s;
        __syncthreads();

        if (threadIdx.x < 32) {
            float v2 = (threadIdx.x < 8) ? sh[threadIdx.x] : 0.0f;
            #pragma unroll
            for (int o = 16; o; o >>= 1)
                v2 += __shfl_xor_sync(0xFFFFFFFFu, v2, o);
            if (threadIdx.x == 0) {
                out[0] = 2.0f - 2.0f * v2 * invB;
                g_count = 0;   // reset for next graph replay
            }
        }
    }
}

extern "C" void kernel_launch(void* const* d_in, const int* in_sizes, int n_in,
                              void* d_out, int out_size)
{
    const float* logits  = (const float*)d_in[0];
    const int*   targets = (const int*)d_in[1];
    float*       out     = (float*)d_out;

    const int B = in_sizes[1];
    const int C = in_sizes[0] / B;

    int grid = (B + RPB - 1) / RPB;        // 16384 for B=131072
    if (grid > MAX_PARTIALS) grid = MAX_PARTIALS;

    mae_kernel<<<grid, 256>>>(logits, targets, out, B, C, 1.0f / (float)B, grid);
}